// round 5
// baseline (speedup 1.0000x reference)
#include <cuda_runtime.h>
#include <cuda_bf16.h>

// Problem constants
#define BB     1024
#define SS     350
#define VOCAB  41
#define LAT    512
#define H1     256
#define H2     128
#define H3     32
#define G0DIM  768
#define G1DIM  384
#define G2DIM  96
#define INITD  416
#define BROWS  8
#define NCTA   128
#define NT     384
#define PRED_OFF (BB*SS*VOCAB)
#define WSM    27            // Whh1 k4-slices kept in smem (of 32)

typedef unsigned long long ull;

// ------------------------- device scratch -----------------------------------
__device__ float  g_G0[VOCAB * G0DIM];
__device__ float  g_init[BB * INITD];
__device__ float4 g_Wt0 [64 * G0DIM];         // Whh0^T  [k4][f], K=256
__device__ float4 g_Wt1 [64 * G1DIM];         // Wih1^T  [k4][f], K=256
__device__ float4 g_Wt1h[32 * G1DIM];         // Whh1^T  [k4][f], K=128
__device__ float4 g_Wt2i[32 * G2DIM];         // Wih2^T  [k4][f], K=128
__device__ float4 g_Wt2h[ 8 * G2DIM];         // Whh2^T  [k4][f], K=32
__device__ float  g_WtInit[LAT * INITD];
__device__ float  g_WtIh0[LAT * G0DIM];

// ------------------------- helpers ------------------------------------------
__device__ __forceinline__ void ffma2(ull &d, ull a, ull b) {
    asm("fma.rn.f32x2 %0, %1, %2, %0;" : "+l"(d) : "l"(a), "l"(b));
}
__device__ __forceinline__ ull packf2(float lo, float hi) {
    ull v; asm("mov.b64 %0, {%1,%2};" : "=l"(v) : "f"(lo), "f"(hi)); return v;
}
__device__ __forceinline__ float hred(ull v) {
    float lo, hi;
    asm("mov.b64 {%0,%1}, %2;" : "=f"(lo), "=f"(hi) : "l"(v));
    return lo + hi;
}
__device__ __forceinline__ float sigf(float x) { return 1.0f / (1.0f + __expf(-x)); }

// ------------------------- prep kernels -------------------------------------
__global__ void k_prep_wt0(const float* __restrict__ Whh0) {
    int idx = blockIdx.x * blockDim.x + threadIdx.x;
    if (idx < G0DIM * 64) {
        int j = idx >> 6, k4 = idx & 63;
        const float* s = Whh0 + j * H1 + k4 * 4;
        g_Wt0[k4 * G0DIM + j] = make_float4(s[0], s[1], s[2], s[3]);
    }
}
__global__ void k_prep_wt1(const float* __restrict__ Wih1) {
    int idx = blockIdx.x * blockDim.x + threadIdx.x;
    if (idx < G1DIM * 64) {
        int j = idx >> 6, k4 = idx & 63;
        const float* s = Wih1 + j * H1 + k4 * 4;
        g_Wt1[k4 * G1DIM + j] = make_float4(s[0], s[1], s[2], s[3]);
    }
}
__global__ void k_prep_wt1h(const float* __restrict__ Whh1) {
    int idx = blockIdx.x * blockDim.x + threadIdx.x;
    if (idx < G1DIM * 32) {
        int j = idx >> 5, k4 = idx & 31;
        const float* s = Whh1 + j * H2 + k4 * 4;
        g_Wt1h[k4 * G1DIM + j] = make_float4(s[0], s[1], s[2], s[3]);
    }
}
__global__ void k_prep_wt2(const float* __restrict__ Wih2, const float* __restrict__ Whh2) {
    int idx = blockIdx.x * blockDim.x + threadIdx.x;
    if (idx < G2DIM * 32) {
        int f = idx >> 5, k4 = idx & 31;
        const float* s = Wih2 + f * H2 + k4 * 4;
        g_Wt2i[k4 * G2DIM + f] = make_float4(s[0], s[1], s[2], s[3]);
    }
    if (idx < G2DIM * 8) {
        int f = idx >> 3, k4 = idx & 7;
        const float* s = Whh2 + f * H3 + k4 * 4;
        g_Wt2h[k4 * G2DIM + f] = make_float4(s[0], s[1], s[2], s[3]);
    }
}
__global__ void k_prep_wtinit(const float* __restrict__ W_init) {
    int idx = blockIdx.x * blockDim.x + threadIdx.x;
    if (idx < INITD * LAT) {
        int o = idx / LAT, k = idx % LAT;
        g_WtInit[k * INITD + o] = W_init[idx];
    }
}
__global__ void k_prep_wtih0(const float* __restrict__ Wih0) {
    int idx = blockIdx.x * blockDim.x + threadIdx.x;
    if (idx < G0DIM * LAT) {
        int j = idx / LAT, k = idx % LAT;
        g_WtIh0[k * G0DIM + j] = Wih0[idx];
    }
}
__global__ void k_g0(const float* __restrict__ W_emb, const float* __restrict__ b_emb,
                     const float* __restrict__ bih0) {
    __shared__ float emb[LAT];
    int v = blockIdx.x;
    for (int k = threadIdx.x; k < LAT; k += blockDim.x)
        emb[k] = W_emb[k * VOCAB + v] + b_emb[k];
    __syncthreads();
    for (int j = threadIdx.x; j < G0DIM; j += blockDim.x) {
        float acc = bih0[j];
        for (int k = 0; k < LAT; k++)
            acc += emb[k] * g_WtIh0[k * G0DIM + j];
        g_G0[v * G0DIM + j] = acc;
    }
}
__global__ void k_init(const float* __restrict__ latent, const float* __restrict__ b_init) {
    __shared__ float lat[8 * LAT];
    int b0 = blockIdx.x * 8;
    for (int i = threadIdx.x; i < 8 * LAT; i += 256) {
        int r = i >> 9, k = i & 511;
        lat[i] = latent[(b0 + r) * LAT + k];
    }
    __syncthreads();
    for (int o = threadIdx.x; o < INITD; o += 256) {
        float bi = b_init[o];
        float acc[8];
#pragma unroll
        for (int r = 0; r < 8; r++) acc[r] = bi;
        for (int k = 0; k < LAT; k++) {
            float w = g_WtInit[k * INITD + o];
#pragma unroll
            for (int r = 0; r < 8; r++) acc[r] += w * lat[(r << 9) + k];
        }
#pragma unroll
        for (int r = 0; r < 8; r++) g_init[(b0 + r) * INITD + o] = acc[r];
    }
}

// ------------------------- main persistent GRU kernel -----------------------
// smem layout (floats)
#define O_WHH1 0                                      // 27*384*4 = 41472 floats
#define O_GA   (WSM * G1DIM * 4)                      // 41472; size 6144
#define O_GB   (O_GA + 6144)                          // 47616; size 3072
#define O_GC   (O_GB + 3072)                          // 50688; size 768
#define O_GN   (O_GC + 768)                           // 51456; size 2048 (gin staging)
#define O_H0   (O_GN + 2048)                          // 53504; 2048
#define O_H1   (O_H0 + BROWS * H1)                    // 55552; 1024
#define O_H2   (O_H1 + BROWS * H2)                    // 56576; 256
#define O_TOK  (O_H2 + BROWS * H3)                    // 56832
#define SMEM_FLOATS (O_TOK + 8)
#define SMEM_BYTES  (SMEM_FLOATS * 4)                 // 227,360 bytes

__global__ void __launch_bounds__(NT, 1)
k_gru(const int* __restrict__ toks,
      const float* __restrict__ bhh0,
      const float* __restrict__ bih1, const float* __restrict__ bhh1,
      const float* __restrict__ bih2, const float* __restrict__ bhh2,
      const float* __restrict__ W_proj, const float* __restrict__ b_proj,
      float* __restrict__ out)
{
    extern __shared__ float sm[];
    float* sGA  = sm + O_GA;
    float* sGB  = sm + O_GB;
    float* sGC  = sm + O_GC;
    float* sGN  = sm + O_GN;      // [r][256] n-gate gi values
    float* h0   = sm + O_H0;
    float* h1   = sm + O_H1;
    float* h2   = sm + O_H2;
    int*   stok = (int*)(sm + O_TOK);

    const int tid  = threadIdx.x;
    const int lane = tid & 31;
    const int wrp  = tid >> 5;
    const int base = blockIdx.x * BROWS;

    // --- load Whh1^T slices 0..26 into smem ---
    {
        float4* d = (float4*)(sm + O_WHH1);
        const float4* s = g_Wt1h;
        for (int i = tid; i < WSM * G1DIM; i += NT) d[i] = s[i];
    }
    // --- initial hidden states ---
    for (int i = tid; i < BROWS * H1; i += NT) {
        int r = i >> 8, k = i & 255;
        h0[i] = g_init[(base + r) * INITD + k];
    }
    for (int i = tid; i < BROWS * H2; i += NT) {
        int r = i >> 7, k = i & 127;
        h1[i] = g_init[(base + r) * INITD + H1 + k];
    }
    for (int i = tid; i < BROWS * H3; i += NT) {
        int r = i >> 5, k = i & 31;
        h2[i] = g_init[(base + r) * INITD + H1 + H2 + k];
    }
    if (tid < BROWS) stok[tid] = 1;   // SOS

    // --- per-thread fixed preloads ---
    const int f0 = tid * 2;
    const float b0a = bhh0[f0], b0b = bhh0[f0 + 1];
    const float b1i = bih1[tid], b1h = bhh1[tid];
    float b2i = 0.0f, b2h = 0.0f;
    if (tid < G2DIM) { b2i = bih2[tid]; b2h = bhh2[tid]; }
    float bp0 = 0.0f, bp1 = 0.0f;
    if (wrp < BROWS) { bp0 = b_proj[lane]; if (lane < 9) bp1 = b_proj[32 + lane]; }
    __syncthreads();

    for (int t = 0; t <= SS; t++) {
        // ===== fused: logits+argmax of step t-1 (warps 0..7) ================
        if (t > 0 && wrp < BROWS) {
            const int r = wrp, b = base + r, tprev = t - 1;
            const float4* hp = (const float4*)(h2 + r * H3);
            float4 hv[8];
#pragma unroll
            for (int q = 0; q < 8; q++) hv[q] = hp[q];
            float acc0 = bp0, acc1 = bp1;
            {
                const float4* wp = (const float4*)(W_proj + lane * H3);
#pragma unroll
                for (int q = 0; q < 8; q++) {
                    float4 w = wp[q];
                    acc0 += w.x * hv[q].x + w.y * hv[q].y + w.z * hv[q].z + w.w * hv[q].w;
                }
            }
            if (lane < 9) {
                const float4* wp = (const float4*)(W_proj + (32 + lane) * H3);
#pragma unroll
                for (int q = 0; q < 8; q++) {
                    float4 w = wp[q];
                    acc1 += w.x * hv[q].x + w.y * hv[q].y + w.z * hv[q].z + w.w * hv[q].w;
                }
            }
            float* orow = out + (size_t)(b * SS + tprev) * VOCAB;
            orow[lane] = acc0;
            if (lane < 9) orow[32 + lane] = acc1;
            float bv = acc0; int bo = lane;
            if (lane < 9 && acc1 > bv) { bv = acc1; bo = 32 + lane; }
#pragma unroll
            for (int off = 16; off; off >>= 1) {
                float ov = __shfl_xor_sync(0xffffffffu, bv, off);
                int   oo = __shfl_xor_sync(0xffffffffu, bo, off);
                if (ov > bv || (ov == bv && oo < bo)) { bv = ov; bo = oo; }
            }
            if (lane == 0) out[PRED_OFF + b * SS + tprev] = (float)bo;
        }
        if (t < SS) {
            // ---- gh0 GEMM: feats f0,f0+1, K=256 over h0 (prefetch 2 k4) ----
            {
                ull a0[BROWS], a1[BROWS];
                if (f0 < 512) {
#pragma unroll
                    for (int r = 0; r < BROWS; r++) {
                        float2 g = *(const float2*)&g_G0[stok[r] * G0DIM + f0];
                        a0[r] = packf2(g.x + b0a, 0.0f);
                        a1[r] = packf2(g.y + b0b, 0.0f);
                    }
                } else {
                    // stage n-gate gi values into smem for combine0
#pragma unroll
                    for (int r = 0; r < BROWS; r++) {
                        float2 g = *(const float2*)&g_G0[stok[r] * G0DIM + f0];
                        *(float2*)&sGN[r * H1 + (f0 - 512)] = g;
                        a0[r] = packf2(b0a, 0.0f);
                        a1[r] = packf2(b0b, 0.0f);
                    }
                }
                const ulonglong2* Wp = (const ulonglong2*)g_Wt0 + f0;
                const ulonglong2* hb = (const ulonglong2*)h0;
#pragma unroll 1
                for (int kk = 0; kk < 32; kk++) {
                    const int kA = 2 * kk, kB = 2 * kk + 1;
                    ulonglong2 wA0 = Wp[0],     wA1 = Wp[1];
                    ulonglong2 wB0 = Wp[G0DIM], wB1 = Wp[G0DIM + 1];
                    Wp += 2 * G0DIM;
                    ull hx[BROWS], hy[BROWS];
#pragma unroll
                    for (int r = 0; r < BROWS; r++) {
                        ulonglong2 hv = hb[r * 64 + kA]; hx[r] = hv.x; hy[r] = hv.y;
                    }
#pragma unroll
                    for (int r = 0; r < BROWS; r++) ffma2(a0[r], wA0.x, hx[r]);
#pragma unroll
                    for (int r = 0; r < BROWS; r++) ffma2(a1[r], wA1.x, hx[r]);
#pragma unroll
                    for (int r = 0; r < BROWS; r++) ffma2(a0[r], wA0.y, hy[r]);
#pragma unroll
                    for (int r = 0; r < BROWS; r++) ffma2(a1[r], wA1.y, hy[r]);
#pragma unroll
                    for (int r = 0; r < BROWS; r++) {
                        ulonglong2 hv = hb[r * 64 + kB]; hx[r] = hv.x; hy[r] = hv.y;
                    }
#pragma unroll
                    for (int r = 0; r < BROWS; r++) ffma2(a0[r], wB0.x, hx[r]);
#pragma unroll
                    for (int r = 0; r < BROWS; r++) ffma2(a1[r], wB1.x, hx[r]);
#pragma unroll
                    for (int r = 0; r < BROWS; r++) ffma2(a0[r], wB0.y, hy[r]);
#pragma unroll
                    for (int r = 0; r < BROWS; r++) ffma2(a1[r], wB1.y, hy[r]);
                }
#pragma unroll
                for (int r = 0; r < BROWS; r++) {
                    sGA[r * G0DIM + f0]     = hred(a0[r]);
                    sGA[r * G0DIM + f0 + 1] = hred(a1[r]);
                }
            }
            // ---- gh1 GEMM: feat tid, K=128 over h1 (smem 27 + gmem 5) ------
            {
                ull a[BROWS];
#pragma unroll
                for (int r = 0; r < BROWS; r++) a[r] = packf2(b1h, 0.0f);
                const ulonglong2* hb = (const ulonglong2*)h1;
                const ulonglong2* Ws = (const ulonglong2*)(sm + O_WHH1) + tid;
#pragma unroll 1
                for (int k4 = 0; k4 < WSM; k4++) {
                    ulonglong2 w = Ws[0]; Ws += G1DIM;
                    ull hx[BROWS], hy[BROWS];
#pragma unroll
                    for (int r = 0; r < BROWS; r++) {
                        ulonglong2 hv = hb[r * 32 + k4]; hx[r] = hv.x; hy[r] = hv.y;
                    }
#pragma unroll
                    for (int r = 0; r < BROWS; r++) ffma2(a[r], w.x, hx[r]);
#pragma unroll
                    for (int r = 0; r < BROWS; r++) ffma2(a[r], w.y, hy[r]);
                }
                const ulonglong2* Wg = (const ulonglong2*)g_Wt1h + WSM * G1DIM + tid;
#pragma unroll 1
                for (int k4 = WSM; k4 < 32; k4++) {
                    ulonglong2 w = Wg[0]; Wg += G1DIM;
                    ull hx[BROWS], hy[BROWS];
#pragma unroll
                    for (int r = 0; r < BROWS; r++) {
                        ulonglong2 hv = hb[r * 32 + k4]; hx[r] = hv.x; hy[r] = hv.y;
                    }
#pragma unroll
                    for (int r = 0; r < BROWS; r++) ffma2(a[r], w.x, hx[r]);
#pragma unroll
                    for (int r = 0; r < BROWS; r++) ffma2(a[r], w.y, hy[r]);
                }
#pragma unroll
                for (int r = 0; r < BROWS; r++) sGB[r * G1DIM + tid] = hred(a[r]);
            }
            // ---- gh2 GEMM: feats 0..95 (tid<96), K=32 over h2 --------------
            if (tid < G2DIM) {
                ull a[BROWS];
#pragma unroll
                for (int r = 0; r < BROWS; r++) a[r] = packf2(b2h, 0.0f);
                const ulonglong2* W  = (const ulonglong2*)g_Wt2h + tid;
                const ulonglong2* hb = (const ulonglong2*)h2;
#pragma unroll
                for (int k4 = 0; k4 < 8; k4++) {
                    ulonglong2 w = W[k4 * G2DIM];
                    ull hx[BROWS], hy[BROWS];
#pragma unroll
                    for (int r = 0; r < BROWS; r++) {
                        ulonglong2 hv = hb[r * 8 + k4]; hx[r] = hv.x; hy[r] = hv.y;
                    }
#pragma unroll
                    for (int r = 0; r < BROWS; r++) ffma2(a[r], w.x, hx[r]);
#pragma unroll
                    for (int r = 0; r < BROWS; r++) ffma2(a[r], w.y, hy[r]);
                }
#pragma unroll
                for (int r = 0; r < BROWS; r++) sGC[r * G2DIM + tid] = hred(a[r]);
            }
        }
        __syncthreads();   // S1

        // ===== combine0: new h0 =====
        if (t < SS) {
            for (int tau = tid; tau < BROWS * H1; tau += NT) {
                int r = tau >> 8, i = tau & 255;
                float pr  = sGA[r * G0DIM + i];
                float pz  = sGA[r * G0DIM + H1 + i];
                float ghn = sGA[r * G0DIM + 2 * H1 + i];
                float gin = sGN[r * H1 + i];
                float rg = sigf(pr), zg = sigf(pz);
                float ng = tanhf(fmaf(rg, ghn, gin));
                float hp = h0[r * H1 + i];
                h0[r * H1 + i] = fmaf(zg, hp - ng, ng);
            }
        }
        __syncthreads();   // S2

        // ===== gi1 GEMM: feat tid, K=256 over new h0 (prefetch 2 k4) =====
        if (t < SS) {
            ull a[BROWS];
#pragma unroll
            for (int r = 0; r < BROWS; r++) a[r] = packf2(b1i, 0.0f);
            const ulonglong2* Wp = (const ulonglong2*)g_Wt1 + tid;
            const ulonglong2* hb = (const ulonglong2*)h0;
#pragma unroll 1
            for (int kk = 0; kk < 32; kk++) {
                const int kA = 2 * kk, kB = 2 * kk + 1;
                ulonglong2 wA = Wp[0];
                ulonglong2 wB = Wp[G1DIM];
                Wp += 2 * G1DIM;
                ull hx[BROWS], hy[BROWS];
#pragma unroll
                for (int r = 0; r < BROWS; r++) {
                    ulonglong2 hv = hb[r * 64 + kA]; hx[r] = hv.x; hy[r] = hv.y;
                }
#pragma unroll
                for (int r = 0; r < BROWS; r++) ffma2(a[r], wA.x, hx[r]);
#pragma unroll
                for (int r = 0; r < BROWS; r++) ffma2(a[r], wA.y, hy[r]);
#pragma unroll
                for (int r = 0; r < BROWS; r++) {
                    ulonglong2 hv = hb[r * 64 + kB]; hx[r] = hv.x; hy[r] = hv.y;
                }
#pragma unroll
                for (int r = 0; r < BROWS; r++) ffma2(a[r], wB.x, hx[r]);
#pragma unroll
                for (int r = 0; r < BROWS; r++) ffma2(a[r], wB.y, hy[r]);
            }
#pragma unroll
            for (int r = 0; r < BROWS; r++) sGA[r * G1DIM + tid] = hred(a[r]);
        }
        __syncthreads();   // S3

        // ===== combine1: new h1 =====
        if (t < SS) {
            for (int tau = tid; tau < BROWS * H2; tau += NT) {
                int r = tau >> 7, j = tau & 127;
                float pr  = sGA[r * G1DIM + j]          + sGB[r * G1DIM + j];
                float pz  = sGA[r * G1DIM + H2 + j]     + sGB[r * G1DIM + H2 + j];
                float gin = sGA[r * G1DIM + 2 * H2 + j];
                float ghn = sGB[r * G1DIM + 2 * H2 + j];
                float rg = sigf(pr), zg = sigf(pz);
                float ng = tanhf(fmaf(rg, ghn, gin));
                float hp = h1[r * H2 + j];
                h1[r * H2 + j] = fmaf(zg, hp - ng, ng);
            }
        }
        __syncthreads();   // S4

        // ===== gi2 GEMM: 96 feats, K=128 over new h1, split-K in 2 =====
        if (t < SS && tid < 2 * G2DIM) {
            const int f  = (tid < G2DIM) ? tid : tid - G2DIM;
            const int k0 = (tid < G2DIM) ? 0 : 16;
            ull a[BROWS];
            ull ini = (tid < G2DIM) ? packf2(b2i, 0.0f) : 0ull;
#pragma unroll
            for (int r = 0; r < BROWS; r++) a[r] = ini;
            const ulonglong2* W  = (const ulonglong2*)g_Wt2i + k0 * G2DIM + f;
            const ulonglong2* hb = (const ulonglong2*)h1;
#pragma unroll 1
            for (int kk = 0; kk < 16; kk++) {
                int k4 = k0 + kk;
                ulonglong2 w = W[0]; W += G2DIM;
                ull hx[BROWS], hy[BROWS];
#pragma unroll
                for (int r = 0; r < BROWS; r++) {
                    ulonglong2 hv = hb[r * 32 + k4]; hx[r] = hv.x; hy[r] = hv.y;
                }
#pragma unroll
                for (int r = 0; r < BROWS; r++) ffma2(a[r], w.x, hx[r]);
#pragma unroll
                for (int r = 0; r < BROWS; r++) ffma2(a[r], w.y, hy[r]);
            }
            float* dst = sGA + ((tid < G2DIM) ? 0 : BROWS * G2DIM);
#pragma unroll
            for (int r = 0; r < BROWS; r++) dst[r * G2DIM + f] = hred(a[r]);
        }
        __syncthreads();   // S5

        // ===== combine2: new h2; prefetch next tokens =====
        if (t < SS) {
            if (tid < BROWS * H3) {
                int r = tid >> 5, i = tid & 31;
                float* A = sGA;
                float* Bp = sGA + BROWS * G2DIM;
                float pr  = A[r * G2DIM + i]          + Bp[r * G2DIM + i]          + sGC[r * G2DIM + i];
                float pz  = A[r * G2DIM + H3 + i]     + Bp[r * G2DIM + H3 + i]     + sGC[r * G2DIM + H3 + i];
                float gin = A[r * G2DIM + 2 * H3 + i] + Bp[r * G2DIM + 2 * H3 + i];
                float ghn = sGC[r * G2DIM + 2 * H3 + i];
                float rg = sigf(pr), zg = sigf(pz);
                float ng = tanhf(fmaf(rg, ghn, gin));
                float hp = h2[r * H3 + i];
                h2[r * H3 + i] = fmaf(zg, hp - ng, ng);
            }
            if (t + 1 < SS && tid < BROWS)
                stok[tid] = toks[(base + tid) * SS + (t + 1)];
        }
        __syncthreads();   // S6
    }
}

// ------------------------- launch -------------------------------------------
extern "C" void kernel_launch(void* const* d_in, const int* in_sizes, int n_in,
                              void* d_out, int out_size) {
    const float* latent  = (const float*)d_in[0];
    const int*   ttok    = (const int*)  d_in[1];
    const float* W_emb   = (const float*)d_in[2];
    const float* b_emb   = (const float*)d_in[3];
    const float* W_init  = (const float*)d_in[4];
    const float* b_init  = (const float*)d_in[5];
    const float* Wih0    = (const float*)d_in[6];
    const float* Whh0    = (const float*)d_in[7];
    const float* bih0    = (const float*)d_in[8];
    const float* bhh0    = (const float*)d_in[9];
    const float* Wih1    = (const float*)d_in[10];
    const float* Whh1    = (const float*)d_in[11];
    const float* bih1    = (const float*)d_in[12];
    const float* bhh1    = (const float*)d_in[13];
    const float* Wih2    = (const float*)d_in[14];
    const float* Whh2    = (const float*)d_in[15];
    const float* bih2    = (const float*)d_in[16];
    const float* bhh2    = (const float*)d_in[17];
    const float* W_proj  = (const float*)d_in[18];
    const float* b_proj  = (const float*)d_in[19];
    float* out = (float*)d_out;

    k_prep_wt0   <<<(G0DIM * 64 + 255) / 256, 256>>>(Whh0);
    k_prep_wt1   <<<(G1DIM * 64 + 255) / 256, 256>>>(Wih1);
    k_prep_wt1h  <<<(G1DIM * 32 + 255) / 256, 256>>>(Whh1);
    k_prep_wt2   <<<(G2DIM * 32 + 255) / 256, 256>>>(Wih2, Whh2);
    k_prep_wtinit<<<(INITD * LAT + 255) / 256, 256>>>(W_init);
    k_prep_wtih0 <<<(G0DIM * LAT + 255) / 256, 256>>>(Wih0);
    k_g0  <<<VOCAB, 256>>>(W_emb, b_emb, bih0);
    k_init<<<BB / 8, 256>>>(latent, b_init);

    cudaFuncSetAttribute(k_gru, cudaFuncAttributeMaxDynamicSharedMemorySize, SMEM_BYTES);
    k_gru<<<NCTA, NT, SMEM_BYTES>>>(ttok, bhh0, bih1, bhh1, bih2, bhh2,
                                    W_proj, b_proj, out);
}

// round 7
// speedup vs baseline: 1.1187x; 1.1187x over previous
#include <cuda_runtime.h>
#include <cuda_bf16.h>

// Problem constants
#define BB     1024
#define SS     350
#define VOCAB  41
#define LAT    512
#define H1     256
#define H2     128
#define H3     32
#define G0DIM  768
#define G1DIM  384
#define G2DIM  96
#define INITD  416
#define BROWS  7
#define NCTA   147           // 147*7 = 1029 >= 1024
#define NT     384
#define PRED_OFF (BB*SS*VOCAB)
#define WSM    28            // Whh1 k4-slices kept in smem (of 32)

typedef unsigned long long ull;

// ------------------------- device scratch -----------------------------------
__device__ float  g_G0[VOCAB * G0DIM];
__device__ float  g_init[BB * INITD];
__device__ float4 g_Wt0 [64 * G0DIM];         // Whh0^T  [k4][f], K=256
__device__ float4 g_Wt1 [64 * G1DIM];         // Wih1^T  [k4][f], K=256
__device__ float4 g_Wt1h[32 * G1DIM];         // Whh1^T  [k4][f], K=128
__device__ float4 g_Wt2i[32 * G2DIM];         // Wih2^T  [k4][f], K=128
__device__ float4 g_Wt2h[ 8 * G2DIM];         // Whh2^T  [k4][f], K=32
__device__ float  g_WtInit[LAT * INITD];
__device__ float  g_WtIh0[LAT * G0DIM];

// ------------------------- helpers ------------------------------------------
__device__ __forceinline__ void ffma2(ull &d, ull a, ull b) {
    asm("fma.rn.f32x2 %0, %1, %2, %0;" : "+l"(d) : "l"(a), "l"(b));
}
__device__ __forceinline__ ull packf2(float lo, float hi) {
    ull v; asm("mov.b64 %0, {%1,%2};" : "=l"(v) : "f"(lo), "f"(hi)); return v;
}
__device__ __forceinline__ float hred(ull v) {
    float lo, hi;
    asm("mov.b64 {%0,%1}, %2;" : "=f"(lo), "=f"(hi) : "l"(v));
    return lo + hi;
}
__device__ __forceinline__ float sigf(float x) { return 1.0f / (1.0f + __expf(-x)); }

// ------------------------- prep kernels -------------------------------------
__global__ void k_prep_wt0(const float* __restrict__ Whh0) {
    int idx = blockIdx.x * blockDim.x + threadIdx.x;
    if (idx < G0DIM * 64) {
        int j = idx >> 6, k4 = idx & 63;
        const float* s = Whh0 + j * H1 + k4 * 4;
        g_Wt0[k4 * G0DIM + j] = make_float4(s[0], s[1], s[2], s[3]);
    }
}
__global__ void k_prep_wt1(const float* __restrict__ Wih1) {
    int idx = blockIdx.x * blockDim.x + threadIdx.x;
    if (idx < G1DIM * 64) {
        int j = idx >> 6, k4 = idx & 63;
        const float* s = Wih1 + j * H1 + k4 * 4;
        g_Wt1[k4 * G1DIM + j] = make_float4(s[0], s[1], s[2], s[3]);
    }
}
__global__ void k_prep_wt1h(const float* __restrict__ Whh1) {
    int idx = blockIdx.x * blockDim.x + threadIdx.x;
    if (idx < G1DIM * 32) {
        int j = idx >> 5, k4 = idx & 31;
        const float* s = Whh1 + j * H2 + k4 * 4;
        g_Wt1h[k4 * G1DIM + j] = make_float4(s[0], s[1], s[2], s[3]);
    }
}
__global__ void k_prep_wt2(const float* __restrict__ Wih2, const float* __restrict__ Whh2) {
    int idx = blockIdx.x * blockDim.x + threadIdx.x;
    if (idx < G2DIM * 32) {
        int f = idx >> 5, k4 = idx & 31;
        const float* s = Wih2 + f * H2 + k4 * 4;
        g_Wt2i[k4 * G2DIM + f] = make_float4(s[0], s[1], s[2], s[3]);
    }
    if (idx < G2DIM * 8) {
        int f = idx >> 3, k4 = idx & 7;
        const float* s = Whh2 + f * H3 + k4 * 4;
        g_Wt2h[k4 * G2DIM + f] = make_float4(s[0], s[1], s[2], s[3]);
    }
}
__global__ void k_prep_wtinit(const float* __restrict__ W_init) {
    int idx = blockIdx.x * blockDim.x + threadIdx.x;
    if (idx < INITD * LAT) {
        int o = idx / LAT, k = idx % LAT;
        g_WtInit[k * INITD + o] = W_init[idx];
    }
}
__global__ void k_prep_wtih0(const float* __restrict__ Wih0) {
    int idx = blockIdx.x * blockDim.x + threadIdx.x;
    if (idx < G0DIM * LAT) {
        int j = idx / LAT, k = idx % LAT;
        g_WtIh0[k * G0DIM + j] = Wih0[idx];
    }
}
__global__ void k_g0(const float* __restrict__ W_emb, const float* __restrict__ b_emb,
                     const float* __restrict__ bih0) {
    __shared__ float emb[LAT];
    int v = blockIdx.x;
    for (int k = threadIdx.x; k < LAT; k += blockDim.x)
        emb[k] = W_emb[k * VOCAB + v] + b_emb[k];
    __syncthreads();
    for (int j = threadIdx.x; j < G0DIM; j += blockDim.x) {
        float acc = bih0[j];
        for (int k = 0; k < LAT; k++)
            acc += emb[k] * g_WtIh0[k * G0DIM + j];
        g_G0[v * G0DIM + j] = acc;
    }
}
__global__ void k_init(const float* __restrict__ latent, const float* __restrict__ b_init) {
    __shared__ float lat[8 * LAT];
    int b0 = blockIdx.x * 8;
    for (int i = threadIdx.x; i < 8 * LAT; i += 256) {
        int r = i >> 9, k = i & 511;
        lat[i] = latent[(b0 + r) * LAT + k];
    }
    __syncthreads();
    for (int o = threadIdx.x; o < INITD; o += 256) {
        float bi = b_init[o];
        float acc[8];
#pragma unroll
        for (int r = 0; r < 8; r++) acc[r] = bi;
        for (int k = 0; k < LAT; k++) {
            float w = g_WtInit[k * INITD + o];
#pragma unroll
            for (int r = 0; r < 8; r++) acc[r] += w * lat[(r << 9) + k];
        }
#pragma unroll
        for (int r = 0; r < 8; r++) g_init[(b0 + r) * INITD + o] = acc[r];
    }
}

// ------------------------- main persistent GRU kernel -----------------------
// smem layout (floats)
#define O_WHH1 0                                      // 28*384*4 = 43008 floats
#define O_GA   (WSM * G1DIM * 4)                      // 43008; size 5376
#define O_GB   (O_GA + BROWS * G0DIM)                 // 48384; size 2688
#define O_GC   (O_GB + BROWS * G1DIM)                 // 51072; size 672
#define O_GN   (O_GC + BROWS * G2DIM)                 // 51744; size 1792
#define O_H0   (O_GN + BROWS * H1)                    // 53536; 1792
#define O_H1   (O_H0 + BROWS * H1)                    // 55328; 896
#define O_H2   (O_H1 + BROWS * H2)                    // 56224; 224
#define O_TOK  (O_H2 + BROWS * H3)                    // 56448
#define SMEM_FLOATS (O_TOK + 8)
#define SMEM_BYTES  (SMEM_FLOATS * 4)                 // 225,824 bytes

__global__ void __launch_bounds__(NT, 1)
k_gru(const int* __restrict__ toks,
      const float* __restrict__ bhh0,
      const float* __restrict__ bih1, const float* __restrict__ bhh1,
      const float* __restrict__ bih2, const float* __restrict__ bhh2,
      const float* __restrict__ W_proj, const float* __restrict__ b_proj,
      float* __restrict__ out)
{
    extern __shared__ float sm[];
    float* sGA  = sm + O_GA;
    float* sGB  = sm + O_GB;
    float* sGC  = sm + O_GC;
    float* sGN  = sm + O_GN;      // [r][256] n-gate gi staging
    float* h0   = sm + O_H0;
    float* h1   = sm + O_H1;
    float* h2   = sm + O_H2;
    int*   stok = (int*)(sm + O_TOK);

    const int tid  = threadIdx.x;
    const int lane = tid & 31;
    const int wrp  = tid >> 5;
    const int base = blockIdx.x * BROWS;

    // --- load Whh1^T slices 0..WSM-1 into smem ---
    {
        float4* d = (float4*)(sm + O_WHH1);
        const float4* s = g_Wt1h;
        for (int i = tid; i < WSM * G1DIM; i += NT) d[i] = s[i];
    }
    // --- initial hidden states (clamped rows) ---
    for (int i = tid; i < BROWS * H1; i += NT) {
        int r = i >> 8, k = i & 255;
        int b = base + r; if (b >= BB) b = BB - 1;
        h0[i] = g_init[b * INITD + k];
    }
    for (int i = tid; i < BROWS * H2; i += NT) {
        int r = i >> 7, k = i & 127;
        int b = base + r; if (b >= BB) b = BB - 1;
        h1[i] = g_init[b * INITD + H1 + k];
    }
    for (int i = tid; i < BROWS * H3; i += NT) {
        int r = i >> 5, k = i & 31;
        int b = base + r; if (b >= BB) b = BB - 1;
        h2[i] = g_init[b * INITD + H1 + H2 + k];
    }
    if (tid < BROWS) stok[tid] = 1;   // SOS

    // --- per-thread fixed preloads ---
    const int f0 = tid * 2;
    const float b0a = bhh0[f0], b0b = bhh0[f0 + 1];
    const float b1i = bih1[tid], b1h = bhh1[tid];
    float b2i = 0.0f, b2h = 0.0f;
    if (tid < G2DIM)                 b2i = bih2[tid];
    if (tid >= 192 && tid < 192 + G2DIM) b2h = bhh2[tid - 192];
    float bp0 = 0.0f, bp1 = 0.0f;
    if (wrp < BROWS) { bp0 = b_proj[lane]; if (lane < 9) bp1 = b_proj[32 + lane]; }
    __syncthreads();

    for (int t = 0; t <= SS; t++) {
        // ===== fused: logits+argmax of step t-1 (warps 0..6) ================
        if (t > 0 && wrp < BROWS) {
            const int r = wrp, b = base + r, tprev = t - 1;
            const float4* hp = (const float4*)(h2 + r * H3);
            float4 hv[8];
#pragma unroll
            for (int q = 0; q < 8; q++) hv[q] = hp[q];
            float acc0 = bp0, acc1 = bp1;
            {
                const float4* wp = (const float4*)(W_proj + lane * H3);
#pragma unroll
                for (int q = 0; q < 8; q++) {
                    float4 w = wp[q];
                    acc0 += w.x * hv[q].x + w.y * hv[q].y + w.z * hv[q].z + w.w * hv[q].w;
                }
            }
            if (lane < 9) {
                const float4* wp = (const float4*)(W_proj + (32 + lane) * H3);
#pragma unroll
                for (int q = 0; q < 8; q++) {
                    float4 w = wp[q];
                    acc1 += w.x * hv[q].x + w.y * hv[q].y + w.z * hv[q].z + w.w * hv[q].w;
                }
            }
            if (b < BB) {
                float* orow = out + (size_t)(b * SS + tprev) * VOCAB;
                orow[lane] = acc0;
                if (lane < 9) orow[32 + lane] = acc1;
            }
            float bv = acc0; int bo = lane;
            if (lane < 9 && acc1 > bv) { bv = acc1; bo = 32 + lane; }
#pragma unroll
            for (int off = 16; off; off >>= 1) {
                float ov = __shfl_xor_sync(0xffffffffu, bv, off);
                int   oo = __shfl_xor_sync(0xffffffffu, bo, off);
                if (ov > bv || (ov == bv && oo < bo)) { bv = ov; bo = oo; }
            }
            if (lane == 0 && b < BB) out[PRED_OFF + b * SS + tprev] = (float)bo;
        }
        if (t < SS) {
            // ---- gh0 GEMM: feats f0,f0+1, K=256 over h0 ----
            {
                ull a0[BROWS], a1[BROWS];
                if (f0 < 512) {
#pragma unroll
                    for (int r = 0; r < BROWS; r++) {
                        float2 g = *(const float2*)&g_G0[stok[r] * G0DIM + f0];
                        a0[r] = packf2(g.x + b0a, 0.0f);
                        a1[r] = packf2(g.y + b0b, 0.0f);
                    }
                } else {
                    // stage n-gate gi values into smem for combine0
#pragma unroll
                    for (int r = 0; r < BROWS; r++) {
                        float2 g = *(const float2*)&g_G0[stok[r] * G0DIM + f0];
                        *(float2*)&sGN[r * H1 + (f0 - 512)] = g;
                        a0[r] = packf2(b0a, 0.0f);
                        a1[r] = packf2(b0b, 0.0f);
                    }
                }
                const ulonglong2* W  = (const ulonglong2*)g_Wt0;
                const ulonglong2* hb = (const ulonglong2*)h0;
#pragma unroll 2
                for (int k4 = 0; k4 < 64; k4++) {
                    ulonglong2 w0 = W[k4 * G0DIM + f0];
                    ulonglong2 w1 = W[k4 * G0DIM + f0 + 1];
#pragma unroll
                    for (int r = 0; r < BROWS; r++) {
                        ulonglong2 hv = hb[r * 64 + k4];
                        ffma2(a0[r], w0.x, hv.x); ffma2(a0[r], w0.y, hv.y);
                        ffma2(a1[r], w1.x, hv.x); ffma2(a1[r], w1.y, hv.y);
                    }
                }
#pragma unroll
                for (int r = 0; r < BROWS; r++) {
                    sGA[r * G0DIM + f0]     = hred(a0[r]);
                    sGA[r * G0DIM + f0 + 1] = hred(a1[r]);
                }
            }
            // ---- gh1 GEMM: feat tid, K=128 over h1 (smem WSM + gmem tail) --
            {
                ull a[BROWS];
#pragma unroll
                for (int r = 0; r < BROWS; r++) a[r] = packf2(b1h, 0.0f);
                const ulonglong2* hb = (const ulonglong2*)h1;
                const ulonglong2* Ws = (const ulonglong2*)(sm + O_WHH1) + tid;
#pragma unroll 2
                for (int k4 = 0; k4 < WSM; k4++) {
                    ulonglong2 w = Ws[(size_t)k4 * G1DIM];
#pragma unroll
                    for (int r = 0; r < BROWS; r++) {
                        ulonglong2 hv = hb[r * 32 + k4];
                        ffma2(a[r], w.x, hv.x); ffma2(a[r], w.y, hv.y);
                    }
                }
                const ulonglong2* Wg = (const ulonglong2*)g_Wt1h + tid;
#pragma unroll
                for (int k4 = WSM; k4 < 32; k4++) {
                    ulonglong2 w = Wg[(size_t)k4 * G1DIM];
#pragma unroll
                    for (int r = 0; r < BROWS; r++) {
                        ulonglong2 hv = hb[r * 32 + k4];
                        ffma2(a[r], w.x, hv.x); ffma2(a[r], w.y, hv.y);
                    }
                }
#pragma unroll
                for (int r = 0; r < BROWS; r++) sGB[r * G1DIM + tid] = hred(a[r]);
            }
        }
        __syncthreads();   // S1

        // ===== combine0: new h0 =====
        if (t < SS) {
            for (int tau = tid; tau < BROWS * H1; tau += NT) {
                int r = tau >> 8, i = tau & 255;
                float pr  = sGA[r * G0DIM + i];
                float pz  = sGA[r * G0DIM + H1 + i];
                float ghn = sGA[r * G0DIM + 2 * H1 + i];
                float gin = sGN[r * H1 + i];
                float rg = sigf(pr), zg = sigf(pz);
                float ng = tanhf(fmaf(rg, ghn, gin));
                float hp = h0[r * H1 + i];
                h0[r * H1 + i] = fmaf(zg, hp - ng, ng);
            }
        }
        __syncthreads();   // S2

        // ===== gi1 GEMM: feat tid, K=256 over new h0 =====
        if (t < SS) {
            ull a[BROWS];
#pragma unroll
            for (int r = 0; r < BROWS; r++) a[r] = packf2(b1i, 0.0f);
            const ulonglong2* W  = (const ulonglong2*)g_Wt1;
            const ulonglong2* hb = (const ulonglong2*)h0;
#pragma unroll 2
            for (int k4 = 0; k4 < 64; k4++) {
                ulonglong2 w = W[k4 * G1DIM + tid];
#pragma unroll
                for (int r = 0; r < BROWS; r++) {
                    ulonglong2 hv = hb[r * 64 + k4];
                    ffma2(a[r], w.x, hv.x); ffma2(a[r], w.y, hv.y);
                }
            }
#pragma unroll
            for (int r = 0; r < BROWS; r++) sGA[r * G1DIM + tid] = hred(a[r]);
        }
        __syncthreads();   // S3

        // ===== combine1: new h1 =====
        if (t < SS) {
            for (int tau = tid; tau < BROWS * H2; tau += NT) {
                int r = tau >> 7, j = tau & 127;
                float pr  = sGA[r * G1DIM + j]          + sGB[r * G1DIM + j];
                float pz  = sGA[r * G1DIM + H2 + j]     + sGB[r * G1DIM + H2 + j];
                float gin = sGA[r * G1DIM + 2 * H2 + j];
                float ghn = sGB[r * G1DIM + 2 * H2 + j];
                float rg = sigf(pr), zg = sigf(pz);
                float ng = tanhf(fmaf(rg, ghn, gin));
                float hp = h1[r * H2 + j];
                h1[r * H2 + j] = fmaf(zg, hp - ng, ng);
            }
        }
        __syncthreads();   // S4

        // ===== gi2 (192 thr, split-K) + gh2 (96 thr) in one phase ==========
        if (t < SS && tid < 192 + G2DIM) {
            if (tid < 2 * G2DIM) {
                const int f  = (tid < G2DIM) ? tid : tid - G2DIM;
                const int k0 = (tid < G2DIM) ? 0 : 16;
                ull a[BROWS];
                ull ini = (tid < G2DIM) ? packf2(b2i, 0.0f) : 0ull;
#pragma unroll
                for (int r = 0; r < BROWS; r++) a[r] = ini;
                const ulonglong2* W  = (const ulonglong2*)g_Wt2i;
                const ulonglong2* hb = (const ulonglong2*)h1;
#pragma unroll 2
                for (int kk = 0; kk < 16; kk++) {
                    int k4 = k0 + kk;
                    ulonglong2 w = W[k4 * G2DIM + f];
#pragma unroll
                    for (int r = 0; r < BROWS; r++) {
                        ulonglong2 hv = hb[r * 32 + k4];
                        ffma2(a[r], w.x, hv.x); ffma2(a[r], w.y, hv.y);
                    }
                }
                float* dst = sGA + ((tid < G2DIM) ? 0 : BROWS * G2DIM);
#pragma unroll
                for (int r = 0; r < BROWS; r++) dst[r * G2DIM + f] = hred(a[r]);
            } else {
                // gh2: feats 0..95 over OLD h2 (K=32)
                const int f = tid - 192;
                ull a[BROWS];
#pragma unroll
                for (int r = 0; r < BROWS; r++) a[r] = packf2(b2h, 0.0f);
                const ulonglong2* W  = (const ulonglong2*)g_Wt2h;
                const ulonglong2* hb = (const ulonglong2*)h2;
#pragma unroll
                for (int k4 = 0; k4 < 8; k4++) {
                    ulonglong2 w = W[k4 * G2DIM + f];
#pragma unroll
                    for (int r = 0; r < BROWS; r++) {
                        ulonglong2 hv = hb[r * 8 + k4];
                        ffma2(a[r], w.x, hv.x); ffma2(a[r], w.y, hv.y);
                    }
                }
#pragma unroll
                for (int r = 0; r < BROWS; r++) sGC[r * G2DIM + f] = hred(a[r]);
            }
        }
        __syncthreads();   // S5

        // ===== combine2: new h2; prefetch next tokens =====
        if (t < SS) {
            if (tid < BROWS * H3) {
                int r = tid >> 5, i = tid & 31;
                float* A  = sGA;
                float* Bp = sGA + BROWS * G2DIM;
                float pr  = A[r * G2DIM + i]          + Bp[r * G2DIM + i]          + sGC[r * G2DIM + i];
                float pz  = A[r * G2DIM + H3 + i]     + Bp[r * G2DIM + H3 + i]     + sGC[r * G2DIM + H3 + i];
                float gin = A[r * G2DIM + 2 * H3 + i] + Bp[r * G2DIM + 2 * H3 + i];
                float ghn = sGC[r * G2DIM + 2 * H3 + i];
                float rg = sigf(pr), zg = sigf(pz);
                float ng = tanhf(fmaf(rg, ghn, gin));
                float hp = h2[r * H3 + i];
                h2[r * H3 + i] = fmaf(zg, hp - ng, ng);
            }
            if (t + 1 < SS && tid < BROWS) {
                int b = base + tid; if (b >= BB) b = BB - 1;
                stok[tid] = toks[b * SS + (t + 1)];
            }
        }
        __syncthreads();   // S6
    }
}

// ------------------------- launch -------------------------------------------
extern "C" void kernel_launch(void* const* d_in, const int* in_sizes, int n_in,
                              void* d_out, int out_size) {
    const float* latent  = (const float*)d_in[0];
    const int*   ttok    = (const int*)  d_in[1];
    const float* W_emb   = (const float*)d_in[2];
    const float* b_emb   = (const float*)d_in[3];
    const float* W_init  = (const float*)d_in[4];
    const float* b_init  = (const float*)d_in[5];
    const float* Wih0    = (const float*)d_in[6];
    const float* Whh0    = (const float*)d_in[7];
    const float* bih0    = (const float*)d_in[8];
    const float* bhh0    = (const float*)d_in[9];
    const float* Wih1    = (const float*)d_in[10];
    const float* Whh1    = (const float*)d_in[11];
    const float* bih1    = (const float*)d_in[12];
    const float* bhh1    = (const float*)d_in[13];
    const float* Wih2    = (const float*)d_in[14];
    const float* Whh2    = (const float*)d_in[15];
    const float* bih2    = (const float*)d_in[16];
    const float* bhh2    = (const float*)d_in[17];
    const float* W_proj  = (const float*)d_in[18];
    const float* b_proj  = (const float*)d_in[19];
    float* out = (float*)d_out;

    k_prep_wt0   <<<(G0DIM * 64 + 255) / 256, 256>>>(Whh0);
    k_prep_wt1   <<<(G1DIM * 64 + 255) / 256, 256>>>(Wih1);
    k_prep_wt1h  <<<(G1DIM * 32 + 255) / 256, 256>>>(Whh1);
    k_prep_wt2   <<<(G2DIM * 32 + 255) / 256, 256>>>(Wih2, Whh2);
    k_prep_wtinit<<<(INITD * LAT + 255) / 256, 256>>>(W_init);
    k_prep_wtih0 <<<(G0DIM * LAT + 255) / 256, 256>>>(Wih0);
    k_g0  <<<VOCAB, 256>>>(W_emb, b_emb, bih0);
    k_init<<<BB / 8, 256>>>(latent, b_init);

    cudaFuncSetAttribute(k_gru, cudaFuncAttributeMaxDynamicSharedMemorySize, SMEM_BYTES);
    k_gru<<<NCTA, NT, SMEM_BYTES>>>(ttok, bhh0, bih1, bhh1, bih2, bhh2,
                                    W_proj, b_proj, out);
}